// round 2
// baseline (speedup 1.0000x reference)
#include <cuda_runtime.h>
#include <cuda_bf16.h>

#define HIDDEN 128
#define NNODES 50000
#define NEDGES 640000

// Scratch (allocation-free rule: device globals)
__device__ float g_AB[NNODES * 256];   // per node: [A(128) | B(128)]
__device__ float g_Wt[128 * 256];      // k-major packed W1: Wt[k][j] (j<128 -> left half, j>=128 -> right half)
__device__ int   g_is64;               // edge_index dtype flag (int64 vs int32)

// ---------------------------------------------------------------------------
// Detect whether edge_index is int64 (high words all zero for values < 50000)
// or int32. Deterministic for a fixed input.
__global__ void detect_kernel(const int* __restrict__ ei) {
    if (threadIdx.x == 0) {
        int all0 = 1;
        #pragma unroll 1
        for (int i = 0; i < 64; i++) {
            if (ei[2 * i + 1] != 0) { all0 = 0; break; }
        }
        g_is64 = all0;
    }
}

// ---------------------------------------------------------------------------
// Pack W1 [128,256] row-major into Wt [128k][256j] so the GEMM reads it
// coalesced:  Wt[k][j]     = W1[j][k]        (j in 0..127)
//             Wt[k][128+j] = W1[j][128+k]
__global__ void pack_w1_kernel(const float* __restrict__ W1) {
    int idx = blockIdx.x * blockDim.x + threadIdx.x;
    if (idx >= 128 * 256) return;
    int k = idx >> 8;
    int j = idx & 255;
    float v = (j < 128) ? W1[j * 256 + k] : W1[(j - 128) * 256 + 128 + k];
    g_Wt[idx] = v;
}

// ---------------------------------------------------------------------------
// AB = Z @ Wt : M=50000, N=256, K=128. fp32 register-tiled SGEMM.
// BM=128, BN=128, BK=8, 256 threads, TM=TN=8.
__global__ __launch_bounds__(256) void gemm_kernel(const float* __restrict__ Z) {
    __shared__ float As[8][128];
    __shared__ float Bs[8][128];

    const int tid = threadIdx.x;
    const int m0 = blockIdx.x * 128;
    const int n0 = blockIdx.y * 128;
    const int tx = tid & 15;   // 0..15 -> N sub-tile
    const int ty = tid >> 4;   // 0..15 -> M sub-tile

    // A-tile global load mapping: each thread loads one float4 of Z
    const int arow = tid >> 1;          // 0..127
    const int acol = (tid & 1) * 4;     // 0 or 4  (k within slab)
    // B-tile global load mapping: one float4 of Wt
    const int bk   = tid >> 5;          // 0..7
    const int bcol = (tid & 31) * 4;    // 0..124

    float acc[8][8];
    #pragma unroll
    for (int i = 0; i < 8; i++)
        #pragma unroll
        for (int j = 0; j < 8; j++) acc[i][j] = 0.0f;

    const int gr_a = m0 + arow;
    const bool a_ok = (gr_a < NNODES);
    const float* zrow = Z + (size_t)gr_a * HIDDEN;

    for (int kk = 0; kk < 128; kk += 8) {
        float4 av = make_float4(0.f, 0.f, 0.f, 0.f);
        if (a_ok) av = *(const float4*)(zrow + kk + acol);
        As[acol + 0][arow] = av.x;
        As[acol + 1][arow] = av.y;
        As[acol + 2][arow] = av.z;
        As[acol + 3][arow] = av.w;

        *(float4*)&Bs[bk][bcol] = *(const float4*)(g_Wt + (kk + bk) * 256 + n0 + bcol);
        __syncthreads();

        #pragma unroll
        for (int k = 0; k < 8; k++) {
            float a[8], b[8];
            *(float4*)&a[0] = *(const float4*)&As[k][ty * 8];
            *(float4*)&a[4] = *(const float4*)&As[k][ty * 8 + 4];
            *(float4*)&b[0] = *(const float4*)&Bs[k][tx * 8];
            *(float4*)&b[4] = *(const float4*)&Bs[k][tx * 8 + 4];
            #pragma unroll
            for (int i = 0; i < 8; i++)
                #pragma unroll
                for (int j = 0; j < 8; j++)
                    acc[i][j] = fmaf(a[i], b[j], acc[i][j]);
        }
        __syncthreads();
    }

    #pragma unroll
    for (int i = 0; i < 8; i++) {
        int gr = m0 + ty * 8 + i;
        if (gr < NNODES) {
            float* orow = g_AB + (size_t)gr * 256 + n0 + tx * 8;
            *(float4*)(orow + 0) = make_float4(acc[i][0], acc[i][1], acc[i][2], acc[i][3]);
            *(float4*)(orow + 4) = make_float4(acc[i][4], acc[i][5], acc[i][6], acc[i][7]);
        }
    }
}

// ---------------------------------------------------------------------------
// Per-edge pass: one warp per edge (grid-stride).
// out[e] = bias2 + sum_j W2[j] * relu(A[src][j] + B[dst][j] + bias1[j])
__global__ __launch_bounds__(256) void edge_kernel(
    const int* __restrict__ ei,
    const float* __restrict__ W2,
    const float* __restrict__ bias1,
    const float* __restrict__ bias2,
    float* __restrict__ out)
{
    const int lane = threadIdx.x & 31;
    const int warp = (blockIdx.x * blockDim.x + threadIdx.x) >> 5;
    const int nwarps = (gridDim.x * blockDim.x) >> 5;
    const int j0 = lane * 4;

    const float4 w2 = *(const float4*)(W2 + j0);
    const float4 b1 = *(const float4*)(bias1 + j0);
    const float b2 = bias2[0];
    const int is64 = g_is64;
    const long long* ei64 = (const long long*)ei;

    for (int e = warp; e < NEDGES; e += nwarps) {
        int src, dst;
        if (is64) {
            src = (int)ei64[e];
            dst = (int)ei64[NEDGES + e];
        } else {
            src = ei[e];
            dst = ei[NEDGES + e];
        }
        float4 a = *(const float4*)(g_AB + (size_t)src * 256 + j0);
        float4 b = *(const float4*)(g_AB + (size_t)dst * 256 + 128 + j0);

        float acc = w2.x * fmaxf(a.x + b.x + b1.x, 0.0f)
                  + w2.y * fmaxf(a.y + b.y + b1.y, 0.0f)
                  + w2.z * fmaxf(a.z + b.z + b1.z, 0.0f)
                  + w2.w * fmaxf(a.w + b.w + b1.w, 0.0f);

        #pragma unroll
        for (int off = 16; off; off >>= 1)
            acc += __shfl_xor_sync(0xffffffffu, acc, off);

        if (lane == 0) out[e] = acc + b2;
    }
}

// ---------------------------------------------------------------------------
extern "C" void kernel_launch(void* const* d_in, const int* in_sizes, int n_in,
                              void* d_out, int out_size) {
    const float* z     = (const float*)d_in[0];   // [50000,128]
    const float* W1    = (const float*)d_in[1];   // [128,256]
    const float* bias1 = (const float*)d_in[2];   // [128]
    const float* W2    = (const float*)d_in[3];   // [1,128]
    const float* bias2 = (const float*)d_in[4];   // [1]
    const int*   ei    = (const int*)d_in[5];     // [2,640000] (int32 or int64, detected)
    float* out = (float*)d_out;

    detect_kernel<<<1, 32>>>(ei);
    pack_w1_kernel<<<(128 * 256 + 255) / 256, 256>>>(W1);

    dim3 ggrid((NNODES + 127) / 128, 2);
    gemm_kernel<<<ggrid, 256>>>(z);

    edge_kernel<<<2368, 256>>>(ei, W2, bias1, bias2, out);
}

// round 3
// speedup vs baseline: 1.4290x; 1.4290x over previous
#include <cuda_runtime.h>
#include <cuda_fp16.h>

#define HIDDEN 128
#define NNODES 50000
#define NEDGES 640000

// Scratch (allocation-free rule: device globals)
__device__ __align__(16) __half g_ABh[NNODES * 256];  // per node: [A+bias1 (128) | B (128)], fp16
__device__ __align__(16) __half g_Wh[128 * 256];      // k-major fp16 W1: Wh[k][j]
__device__ __align__(16) int2   g_sd[NEDGES];         // decoded (src,dst) per edge
__device__ int g_is64;

// ---------------------------------------------------------------------------
__global__ void detect_kernel(const int* __restrict__ ei) {
    if (threadIdx.x == 0) {
        int all0 = 1;
        #pragma unroll 1
        for (int i = 0; i < 64; i++) {
            if (ei[2 * i + 1] != 0) { all0 = 0; break; }
        }
        g_is64 = all0;
    }
}

// Decode edge index (int64 or int32) into int2 pairs.
__global__ __launch_bounds__(256) void prep_kernel(const int* __restrict__ ei) {
    int i = blockIdx.x * blockDim.x + threadIdx.x;
    if (i >= NEDGES) return;
    int src, dst;
    if (g_is64) {
        const long long* e64 = (const long long*)ei;
        src = (int)e64[i];
        dst = (int)e64[NEDGES + i];
    } else {
        src = ei[i];
        dst = ei[NEDGES + i];
    }
    g_sd[i] = make_int2(src, dst);
}

// Pack W1 [128,256] row-major into fp16 k-major Wh[k][j]:
//   Wh[k][j]     = W1[j][k]          (j <128)
//   Wh[k][128+j] = W1[j][128+k]
__global__ __launch_bounds__(256) void pack_w1_kernel(const float* __restrict__ W1) {
    int idx = blockIdx.x * blockDim.x + threadIdx.x;  // 128*256 threads
    int k = idx >> 8;
    int j = idx & 255;
    float v = (j < 128) ? W1[j * 256 + k] : W1[(j - 128) * 256 + 128 + k];
    g_Wh[idx] = __float2half_rn(v);
}

// ---------------------------------------------------------------------------
// AB = Z @ Wh via tensor cores. M=50000, N=256 (grid.y 2 x 128), K=128.
// Block 128x128, 256 threads = 8 warps (4 m x 2 n), warp tile 32x64.
// Whole K resident in smem (one sync). Padded rows (136 halves) for
// conflict-free ldmatrix. fp16 inputs, fp32 accumulate, fp16 output, bias1
// folded into the first 128 columns.
#define SROW 136

__device__ __forceinline__ void mma16816(float* d, unsigned a0, unsigned a1,
                                         unsigned a2, unsigned a3,
                                         unsigned b0, unsigned b1) {
    asm volatile(
        "mma.sync.aligned.m16n8k16.row.col.f32.f16.f16.f32 "
        "{%0,%1,%2,%3}, {%4,%5,%6,%7}, {%8,%9}, {%0,%1,%2,%3};"
        : "+f"(d[0]), "+f"(d[1]), "+f"(d[2]), "+f"(d[3])
        : "r"(a0), "r"(a1), "r"(a2), "r"(a3), "r"(b0), "r"(b1));
}

__global__ __launch_bounds__(256) void gemm_kernel(const float* __restrict__ Z,
                                                   const float* __restrict__ bias1) {
    extern __shared__ __half sm[];
    __half* As = sm;               // [128][SROW]
    __half* Bs = sm + 128 * SROW;  // [128][SROW]

    const int tid = threadIdx.x;
    const int m0 = blockIdx.x * 128;
    const int yhalf = blockIdx.y;  // 0: A+bias half, 1: B half

    // ---- load A tile: Z[m0..m0+127][0..127] fp32 -> fp16 smem ----
    {
        int row = tid >> 1;
        int c0 = (tid & 1) * 64;
        int gr = m0 + row;
        if (gr < NNODES) {
            const float* zr = Z + (size_t)gr * HIDDEN + c0;
            __half* dst = As + row * SROW + c0;
            #pragma unroll
            for (int i = 0; i < 16; i++) {
                float4 v = *(const float4*)(zr + i * 4);
                __half2* d2 = (__half2*)(dst + i * 4);
                d2[0] = __floats2half2_rn(v.x, v.y);
                d2[1] = __floats2half2_rn(v.z, v.w);
            }
        } else {
            __half2 z2 = __float2half2_rn(0.f);
            __half2* d2 = (__half2*)(As + row * SROW + c0);
            #pragma unroll
            for (int i = 0; i < 32; i++) d2[i] = z2;
        }
    }
    // ---- load B tile: Wh[0..127][n0..n0+127] fp16 smem ----
    {
        int row = tid >> 1;
        int c0 = (tid & 1) * 64;
        const uint4* src = (const uint4*)(g_Wh + row * 256 + yhalf * 128 + c0);
        uint4* dst = (uint4*)(Bs + row * SROW + c0);
        #pragma unroll
        for (int i = 0; i < 8; i++) dst[i] = src[i];
    }
    __syncthreads();

    const int wid = tid >> 5;
    const int lane = tid & 31;
    const int warp_m = wid >> 1;           // 0..3
    const int warp_n = wid & 1;            // 0..1
    const int mbase = warp_m * 32;
    const int nbase = warp_n * 64;
    const int g = lane >> 2;
    const int tq = lane & 3;

    float acc[2][8][4];
    #pragma unroll
    for (int mi = 0; mi < 2; mi++)
        #pragma unroll
        for (int ni = 0; ni < 8; ni++)
            #pragma unroll
            for (int c = 0; c < 4; c++) acc[mi][ni][c] = 0.f;

    // ldmatrix lane-address components
    const int a_row_l = lane & 15;
    const int a_col_l = (lane >> 4) << 3;
    const int b_row_l = lane & 15;

    #pragma unroll
    for (int kc = 0; kc < 8; kc++) {
        unsigned a[2][4];
        #pragma unroll
        for (int mi = 0; mi < 2; mi++) {
            const __half* p = As + (mbase + mi * 16 + a_row_l) * SROW + kc * 16 + a_col_l;
            unsigned sa = (unsigned)__cvta_generic_to_shared(p);
            asm volatile("ldmatrix.sync.aligned.m8n8.x4.shared.b16 {%0,%1,%2,%3}, [%4];"
                         : "=r"(a[mi][0]), "=r"(a[mi][1]), "=r"(a[mi][2]), "=r"(a[mi][3])
                         : "r"(sa));
        }
        unsigned b[8][2];
        #pragma unroll
        for (int ni = 0; ni < 8; ni++) {
            const __half* p = Bs + (kc * 16 + b_row_l) * SROW + nbase + ni * 8;
            unsigned sb = (unsigned)__cvta_generic_to_shared(p);
            asm volatile("ldmatrix.sync.aligned.m8n8.x2.trans.shared.b16 {%0,%1}, [%2];"
                         : "=r"(b[ni][0]), "=r"(b[ni][1])
                         : "r"(sb));
        }
        #pragma unroll
        for (int mi = 0; mi < 2; mi++)
            #pragma unroll
            for (int ni = 0; ni < 8; ni++)
                mma16816(acc[mi][ni], a[mi][0], a[mi][1], a[mi][2], a[mi][3],
                         b[ni][0], b[ni][1]);
    }

    // ---- epilogue: +bias1 (first half only), fp16 store ----
    #pragma unroll
    for (int ni = 0; ni < 8; ni++) {
        int ncol = nbase + ni * 8 + tq * 2;  // local n 0..127
        float bx = 0.f, by = 0.f;
        if (yhalf == 0) { bx = bias1[ncol]; by = bias1[ncol + 1]; }
        size_t colg = (size_t)yhalf * 128 + ncol;
        #pragma unroll
        for (int mi = 0; mi < 2; mi++) {
            int r0 = m0 + mbase + mi * 16 + g;
            if (r0 < NNODES) {
                *(__half2*)(g_ABh + (size_t)r0 * 256 + colg) =
                    __floats2half2_rn(acc[mi][ni][0] + bx, acc[mi][ni][1] + by);
            }
            int r1 = r0 + 8;
            if (r1 < NNODES) {
                *(__half2*)(g_ABh + (size_t)r1 * 256 + colg) =
                    __floats2half2_rn(acc[mi][ni][2] + bx, acc[mi][ni][3] + by);
            }
        }
    }
}

// ---------------------------------------------------------------------------
// Per-edge pass: 16 lanes per edge, 2 edges per warp.
// out[e] = bias2 + sum_j W2[j] * relu(A'[src][j] + B[dst][j])   (bias1 in A')
__global__ __launch_bounds__(256) void edge_kernel(
    const float* __restrict__ W2,
    const float* __restrict__ bias2,
    float* __restrict__ out)
{
    const int lane = threadIdx.x & 31;
    const int sl = lane & 15;
    const int sub = lane >> 4;
    const int w = (blockIdx.x * blockDim.x + threadIdx.x) >> 5;
    const int nw = (gridDim.x * blockDim.x) >> 5;

    const float4 w2a = *(const float4*)(W2 + sl * 8);
    const float4 w2b = *(const float4*)(W2 + sl * 8 + 4);
    const float b2 = bias2[0];
    const __half2 zero2 = __float2half2_rn(0.f);

    for (int base = 2 * w; base < NEDGES; base += 2 * nw) {
        const int e = base + sub;
        int2 sd = g_sd[e];
        uint4 av = *(const uint4*)(g_ABh + (size_t)sd.x * 256 + sl * 8);
        uint4 bv = *(const uint4*)(g_ABh + (size_t)sd.y * 256 + 128 + sl * 8);
        const __half2* ah = (const __half2*)&av;
        const __half2* bh = (const __half2*)&bv;

        float2 f0 = __half22float2(__hmax2(__hadd2(ah[0], bh[0]), zero2));
        float2 f1 = __half22float2(__hmax2(__hadd2(ah[1], bh[1]), zero2));
        float2 f2 = __half22float2(__hmax2(__hadd2(ah[2], bh[2]), zero2));
        float2 f3 = __half22float2(__hmax2(__hadd2(ah[3], bh[3]), zero2));

        float acc = w2a.x * f0.x + w2a.y * f0.y + w2a.z * f1.x + w2a.w * f1.y
                  + w2b.x * f2.x + w2b.y * f2.y + w2b.z * f3.x + w2b.w * f3.y;

        acc += __shfl_xor_sync(0xffffffffu, acc, 1);
        acc += __shfl_xor_sync(0xffffffffu, acc, 2);
        acc += __shfl_xor_sync(0xffffffffu, acc, 4);
        acc += __shfl_xor_sync(0xffffffffu, acc, 8);

        if (sl == 0) out[e] = acc + b2;
    }
}

// ---------------------------------------------------------------------------
extern "C" void kernel_launch(void* const* d_in, const int* in_sizes, int n_in,
                              void* d_out, int out_size) {
    const float* z     = (const float*)d_in[0];   // [50000,128]
    const float* W1    = (const float*)d_in[1];   // [128,256]
    const float* bias1 = (const float*)d_in[2];   // [128]
    const float* W2    = (const float*)d_in[3];   // [1,128]
    const float* bias2 = (const float*)d_in[4];   // [1]
    const int*   ei    = (const int*)d_in[5];     // [2,640000]
    float* out = (float*)d_out;

    static int smem_set = 0;
    const int smem_bytes = 2 * 128 * SROW * (int)sizeof(__half);
    if (!smem_set) {
        cudaFuncSetAttribute(gemm_kernel,
                             cudaFuncAttributeMaxDynamicSharedMemorySize, smem_bytes);
        smem_set = 1;
    }

    detect_kernel<<<1, 32>>>(ei);
    prep_kernel<<<(NEDGES + 255) / 256, 256>>>(ei);
    pack_w1_kernel<<<128, 256>>>(W1);

    dim3 ggrid((NNODES + 127) / 128, 2);
    gemm_kernel<<<ggrid, 256, smem_bytes>>>(z, bias1);

    edge_kernel<<<2368, 256>>>(W2, bias2, out);
}

// round 4
// speedup vs baseline: 2.7006x; 1.8899x over previous
#include <cuda_runtime.h>
#include <cuda_fp16.h>

#define HIDDEN 128
#define NNODES 50000
#define NEDGES 640000

// Scratch (allocation-free rule: device globals)
__device__ __align__(16) __half g_ABh[NNODES * 256];  // per node: [A+bias1 (128) | B (128)], fp16
__device__ __align__(16) __half g_Zh[NNODES * 128];   // fp16 copy of z
__device__ __align__(16) __half g_Wh[128 * 256];      // k-major fp16 W1: Wh[k][j]
__device__ __align__(16) int2   g_sd[NEDGES];         // decoded (src,dst) per edge
__device__ int g_is64;

// ---------------------------------------------------------------------------
// Parallel dtype detect: 32 probes, one ballot. ~2us instead of ~20us serial.
__global__ void detect_kernel(const int* __restrict__ ei) {
    unsigned m = __ballot_sync(0xffffffffu, ei[2 * threadIdx.x + 1] != 0);
    if (threadIdx.x == 0) g_is64 = (m == 0) ? 1 : 0;
}

// ---------------------------------------------------------------------------
// Fused prep: edge decode + Z fp32->fp16 convert + W1 pack, partitioned by block.
#define PREP_EDGE_BLOCKS 2500                       // 640000 / 256
#define CONV_BLOCKS 1563                            // 50000*128 / (256*16) rounded up
#define PACK_BLOCKS 128                             // 128*256 / 256
#define PREP_TOTAL_BLOCKS (PREP_EDGE_BLOCKS + CONV_BLOCKS + PACK_BLOCKS)

__global__ __launch_bounds__(256) void prep_all_kernel(
    const int* __restrict__ ei, const float* __restrict__ Z,
    const float* __restrict__ W1)
{
    const int b = blockIdx.x;
    if (b < PREP_EDGE_BLOCKS) {
        int i = b * 256 + threadIdx.x;
        if (i < NEDGES) {
            int src, dst;
            if (g_is64) {
                const long long* e64 = (const long long*)ei;
                src = (int)e64[i];
                dst = (int)e64[NEDGES + i];
            } else {
                src = ei[i];
                dst = ei[NEDGES + i];
            }
            g_sd[i] = make_int2(src, dst);
        }
    } else if (b < PREP_EDGE_BLOCKS + CONV_BLOCKS) {
        // 16 floats per thread
        size_t base = ((size_t)(b - PREP_EDGE_BLOCKS) * 256 + threadIdx.x) * 16;
        if (base < (size_t)NNODES * 128) {
            const float4* src = (const float4*)(Z + base);
            __half2 h[8];
            #pragma unroll
            for (int i = 0; i < 4; i++) {
                float4 v = src[i];
                h[2 * i]     = __floats2half2_rn(v.x, v.y);
                h[2 * i + 1] = __floats2half2_rn(v.z, v.w);
            }
            uint4* dst = (uint4*)(g_Zh + base);
            dst[0] = *(const uint4*)&h[0];
            dst[1] = *(const uint4*)&h[4];
        }
    } else {
        // pack W1: Wh[k][j] = W1[j][k] (j<128), Wh[k][128+j] = W1[j][128+k]
        int idx = (b - PREP_EDGE_BLOCKS - CONV_BLOCKS) * 256 + threadIdx.x;
        int k = idx >> 8;
        int j = idx & 255;
        float v = (j < 128) ? W1[j * 256 + k] : W1[(j - 128) * 256 + 128 + k];
        g_Wh[idx] = __float2half_rn(v);
    }
}

// ---------------------------------------------------------------------------
// Pipelined tensor-core GEMM: AB = Zh @ Wh. M=50000, N=256 (grid.y 2 x 128),
// K=128 in 4 cp.async stages of 32. B tile (full 128x128) + A stage 0 are
// commit-group 0; A stages 1..3 are groups 1..3. Compute of stage s begins
// after wait_group(3-s). Block 128x128, 8 warps (4m x 2n), warp tile 32x64.
#define AS_ROW 40    // halves per A smem row: 32 data + 8 pad (conflict-free ldmatrix)
#define BS_ROW 136   // halves per B smem row: 128 data + 8 pad
#define GEMM_SMEM ((128 * BS_ROW + 4 * 128 * AS_ROW) * 2)  // 75776 bytes

__device__ __forceinline__ void cp16(__half* dst, const __half* src, int src_bytes) {
    unsigned d = (unsigned)__cvta_generic_to_shared(dst);
    asm volatile("cp.async.cg.shared.global [%0], [%1], 16, %2;"
                 :: "r"(d), "l"(src), "r"(src_bytes));
}

__device__ __forceinline__ void mma16816(float* d, unsigned a0, unsigned a1,
                                         unsigned a2, unsigned a3,
                                         unsigned b0, unsigned b1) {
    asm volatile(
        "mma.sync.aligned.m16n8k16.row.col.f32.f16.f16.f32 "
        "{%0,%1,%2,%3}, {%4,%5,%6,%7}, {%8,%9}, {%0,%1,%2,%3};"
        : "+f"(d[0]), "+f"(d[1]), "+f"(d[2]), "+f"(d[3])
        : "r"(a0), "r"(a1), "r"(a2), "r"(a3), "r"(b0), "r"(b1));
}

__global__ __launch_bounds__(256) void gemm_kernel(const float* __restrict__ bias1) {
    extern __shared__ __half sm[];
    __half* Bs = sm;                    // [128][BS_ROW]
    __half* As = sm + 128 * BS_ROW;     // [4][128][AS_ROW]

    const int tid = threadIdx.x;
    const int m0 = blockIdx.x * 128;
    const int yhalf = blockIdx.y;       // 0: A+bias half, 1: B half

    // ---- issue B tile: 128 k-rows x 16 chunks of 16B; 8 chunks/thread ----
    #pragma unroll
    for (int i = 0; i < 8; i++) {
        int ch = tid + i * 256;
        int k = ch >> 4, cc = ch & 15;
        cp16(Bs + k * BS_ROW + cc * 8, g_Wh + k * 256 + yhalf * 128 + cc * 8, 16);
    }
    // ---- issue A stages: each 128 rows x 4 chunks of 16B; 2 chunks/thread ----
    #pragma unroll
    for (int s = 0; s < 4; s++) {
        #pragma unroll
        for (int i = 0; i < 2; i++) {
            int ch = tid + i * 256;
            int row = ch >> 2, cc = ch & 3;
            int gr = m0 + row;
            int ok = (gr < NNODES);
            const __half* src = g_Zh + (size_t)(ok ? gr : 0) * 128 + s * 32 + cc * 8;
            cp16(As + (s * 128 + row) * AS_ROW + cc * 8, src, ok ? 16 : 0);
        }
        asm volatile("cp.async.commit_group;");
    }

    const int wid = tid >> 5;
    const int lane = tid & 31;
    const int mbase = (wid >> 1) * 32;
    const int nbase = (wid & 1) * 64;
    const int g = lane >> 2;
    const int tq = lane & 3;
    const int row_l = lane & 15;
    const int a_hi = (lane >> 4) << 3;

    float acc[2][8][4];
    #pragma unroll
    for (int mi = 0; mi < 2; mi++)
        #pragma unroll
        for (int ni = 0; ni < 8; ni++)
            #pragma unroll
            for (int c = 0; c < 4; c++) acc[mi][ni][c] = 0.f;

    #pragma unroll
    for (int s = 0; s < 4; s++) {
        if (s == 0)      asm volatile("cp.async.wait_group 3;" ::: "memory");
        else if (s == 1) asm volatile("cp.async.wait_group 2;" ::: "memory");
        else if (s == 2) asm volatile("cp.async.wait_group 1;" ::: "memory");
        else             asm volatile("cp.async.wait_group 0;" ::: "memory");
        __syncthreads();

        const __half* Ab = As + s * 128 * AS_ROW;
        #pragma unroll
        for (int ks = 0; ks < 2; ks++) {
            unsigned a[2][4];
            #pragma unroll
            for (int mi = 0; mi < 2; mi++) {
                const __half* p = Ab + (mbase + mi * 16 + row_l) * AS_ROW + ks * 16 + a_hi;
                unsigned sa = (unsigned)__cvta_generic_to_shared(p);
                asm volatile("ldmatrix.sync.aligned.m8n8.x4.shared.b16 {%0,%1,%2,%3}, [%4];"
                             : "=r"(a[mi][0]), "=r"(a[mi][1]), "=r"(a[mi][2]), "=r"(a[mi][3])
                             : "r"(sa));
            }
            unsigned bf[8][2];
            #pragma unroll
            for (int ni = 0; ni < 8; ni++) {
                const __half* p = Bs + (s * 32 + ks * 16 + row_l) * BS_ROW + nbase + ni * 8;
                unsigned sb = (unsigned)__cvta_generic_to_shared(p);
                asm volatile("ldmatrix.sync.aligned.m8n8.x2.trans.shared.b16 {%0,%1}, [%2];"
                             : "=r"(bf[ni][0]), "=r"(bf[ni][1])
                             : "r"(sb));
            }
            #pragma unroll
            for (int mi = 0; mi < 2; mi++)
                #pragma unroll
                for (int ni = 0; ni < 8; ni++)
                    mma16816(acc[mi][ni], a[mi][0], a[mi][1], a[mi][2], a[mi][3],
                             bf[ni][0], bf[ni][1]);
        }
    }

    // ---- epilogue: +bias1 (first half only), fp16 store ----
    #pragma unroll
    for (int ni = 0; ni < 8; ni++) {
        int ncol = nbase + ni * 8 + tq * 2;
        float bx = 0.f, by = 0.f;
        if (yhalf == 0) { bx = bias1[ncol]; by = bias1[ncol + 1]; }
        size_t colg = (size_t)yhalf * 128 + ncol;
        #pragma unroll
        for (int mi = 0; mi < 2; mi++) {
            int r0 = m0 + mbase + mi * 16 + g;
            if (r0 < NNODES) {
                *(__half2*)(g_ABh + (size_t)r0 * 256 + colg) =
                    __floats2half2_rn(acc[mi][ni][0] + bx, acc[mi][ni][1] + by);
            }
            int r1 = r0 + 8;
            if (r1 < NNODES) {
                *(__half2*)(g_ABh + (size_t)r1 * 256 + colg) =
                    __floats2half2_rn(acc[mi][ni][2] + bx, acc[mi][ni][3] + by);
            }
        }
    }
}

// ---------------------------------------------------------------------------
// Per-edge pass: 16 lanes per edge, 2 edges per warp.
// out[e] = bias2 + sum_j W2[j] * relu(A'[src][j] + B[dst][j])   (bias1 in A')
__global__ __launch_bounds__(256) void edge_kernel(
    const float* __restrict__ W2,
    const float* __restrict__ bias2,
    float* __restrict__ out)
{
    const int lane = threadIdx.x & 31;
    const int sl = lane & 15;
    const int sub = lane >> 4;
    const int w = (blockIdx.x * blockDim.x + threadIdx.x) >> 5;
    const int nw = (gridDim.x * blockDim.x) >> 5;

    const float4 w2a = *(const float4*)(W2 + sl * 8);
    const float4 w2b = *(const float4*)(W2 + sl * 8 + 4);
    const float b2 = bias2[0];
    const __half2 zero2 = __float2half2_rn(0.f);

    for (int base = 2 * w; base < NEDGES; base += 2 * nw) {
        const int e = base + sub;
        int2 sd = g_sd[e];
        uint4 av = *(const uint4*)(g_ABh + (size_t)sd.x * 256 + sl * 8);
        uint4 bv = *(const uint4*)(g_ABh + (size_t)sd.y * 256 + 128 + sl * 8);
        const __half2* ah = (const __half2*)&av;
        const __half2* bh = (const __half2*)&bv;

        float2 f0 = __half22float2(__hmax2(__hadd2(ah[0], bh[0]), zero2));
        float2 f1 = __half22float2(__hmax2(__hadd2(ah[1], bh[1]), zero2));
        float2 f2 = __half22float2(__hmax2(__hadd2(ah[2], bh[2]), zero2));
        float2 f3 = __half22float2(__hmax2(__hadd2(ah[3], bh[3]), zero2));

        float acc = w2a.x * f0.x + w2a.y * f0.y + w2a.z * f1.x + w2a.w * f1.y
                  + w2b.x * f2.x + w2b.y * f2.y + w2b.z * f3.x + w2b.w * f3.y;

        acc += __shfl_xor_sync(0xffffffffu, acc, 1);
        acc += __shfl_xor_sync(0xffffffffu, acc, 2);
        acc += __shfl_xor_sync(0xffffffffu, acc, 4);
        acc += __shfl_xor_sync(0xffffffffu, acc, 8);

        if (sl == 0) out[e] = acc + b2;
    }
}

// ---------------------------------------------------------------------------
extern "C" void kernel_launch(void* const* d_in, const int* in_sizes, int n_in,
                              void* d_out, int out_size) {
    const float* z     = (const float*)d_in[0];   // [50000,128]
    const float* W1    = (const float*)d_in[1];   // [128,256]
    const float* bias1 = (const float*)d_in[2];   // [128]
    const float* W2    = (const float*)d_in[3];   // [1,128]
    const float* bias2 = (const float*)d_in[4];   // [1]
    const int*   ei    = (const int*)d_in[5];     // [2,640000]
    float* out = (float*)d_out;

    static int smem_set = 0;
    if (!smem_set) {
        cudaFuncSetAttribute(gemm_kernel,
                             cudaFuncAttributeMaxDynamicSharedMemorySize, GEMM_SMEM);
        smem_set = 1;
    }

    detect_kernel<<<1, 32>>>(ei);
    prep_all_kernel<<<PREP_TOTAL_BLOCKS, 256>>>(ei, z, W1);

    dim3 ggrid((NNODES + 127) / 128, 2);
    gemm_kernel<<<ggrid, 256, GEMM_SMEM>>>(bias1);

    edge_kernel<<<2368, 256>>>(W2, bias2, out);
}

// round 5
// speedup vs baseline: 2.7854x; 1.0314x over previous
#include <cuda_runtime.h>
#include <cuda_fp16.h>

#define HIDDEN 128
#define NNODES 50000
#define NEDGES 640000

// Scratch (allocation-free rule: device globals)
__device__ __align__(16) __half g_ABh[NNODES * 256];  // per node: [A+bias1 (128) | B (128)], fp16
__device__ __align__(16) __half g_Zh[NNODES * 128];   // fp16 copy of z
__device__ __align__(16) __half g_Wh[128 * 256];      // k-major fp16 W1: Wh[k][j]
__device__ int g_is64;

// ---------------------------------------------------------------------------
// Fused prep: block 0 = dtype detect, then Z fp32->fp16 convert, then W1 pack.
#define CONV_BLOCKS 1563                            // 50000*128 / (256*16) rounded up
#define PACK_BLOCKS 128                             // 128*256 / 256
#define PREP_TOTAL_BLOCKS (1 + CONV_BLOCKS + PACK_BLOCKS)

__global__ __launch_bounds__(256) void prep_all_kernel(
    const int* __restrict__ ei, const float* __restrict__ Z,
    const float* __restrict__ W1)
{
    const int b = blockIdx.x;
    if (b == 0) {
        // dtype detect: if input is int64 with values < 2^31, every odd word is 0.
        if (threadIdx.x < 32) {
            unsigned m = __ballot_sync(0xffffffffu, ei[2 * threadIdx.x + 1] != 0);
            if (threadIdx.x == 0) g_is64 = (m == 0) ? 1 : 0;
        }
    } else if (b <= CONV_BLOCKS) {
        // Z fp32 -> fp16: 16 floats per thread
        size_t base = ((size_t)(b - 1) * 256 + threadIdx.x) * 16;
        if (base < (size_t)NNODES * 128) {
            const float4* src = (const float4*)(Z + base);
            __half2 h[8];
            #pragma unroll
            for (int i = 0; i < 4; i++) {
                float4 v = src[i];
                h[2 * i]     = __floats2half2_rn(v.x, v.y);
                h[2 * i + 1] = __floats2half2_rn(v.z, v.w);
            }
            uint4* dst = (uint4*)(g_Zh + base);
            dst[0] = *(const uint4*)&h[0];
            dst[1] = *(const uint4*)&h[4];
        }
    } else {
        // pack W1: Wh[k][j] = W1[j][k] (j<128), Wh[k][128+j] = W1[j][128+k]
        int idx = (b - 1 - CONV_BLOCKS) * 256 + threadIdx.x;
        int k = idx >> 8;
        int j = idx & 255;
        float v = (j < 128) ? W1[j * 256 + k] : W1[(j - 128) * 256 + 128 + k];
        g_Wh[idx] = __float2half_rn(v);
    }
}

// ---------------------------------------------------------------------------
// Pipelined tensor-core GEMM: AB = Zh @ Wh. M=50000, N=256 (grid.y 2 x 128),
// K=128 in 4 cp.async stages of 32. B tile (full 128x128) + A stage 0 are
// commit-group 0; A stages 1..3 are groups 1..3. Compute of stage s begins
// after wait_group(3-s). Block 128x128, 8 warps (4m x 2n), warp tile 32x64.
#define AS_ROW 40    // halves per A smem row: 32 data + 8 pad (conflict-free ldmatrix)
#define BS_ROW 136   // halves per B smem row: 128 data + 8 pad
#define GEMM_SMEM ((128 * BS_ROW + 4 * 128 * AS_ROW) * 2)  // 75776 bytes

__device__ __forceinline__ void cp16(__half* dst, const __half* src, int src_bytes) {
    unsigned d = (unsigned)__cvta_generic_to_shared(dst);
    asm volatile("cp.async.cg.shared.global [%0], [%1], 16, %2;"
                 :: "r"(d), "l"(src), "r"(src_bytes));
}

__device__ __forceinline__ void mma16816(float* d, unsigned a0, unsigned a1,
                                         unsigned a2, unsigned a3,
                                         unsigned b0, unsigned b1) {
    asm volatile(
        "mma.sync.aligned.m16n8k16.row.col.f32.f16.f16.f32 "
        "{%0,%1,%2,%3}, {%4,%5,%6,%7}, {%8,%9}, {%0,%1,%2,%3};"
        : "+f"(d[0]), "+f"(d[1]), "+f"(d[2]), "+f"(d[3])
        : "r"(a0), "r"(a1), "r"(a2), "r"(a3), "r"(b0), "r"(b1));
}

__global__ __launch_bounds__(256) void gemm_kernel(const float* __restrict__ bias1) {
    extern __shared__ __half sm[];
    __half* Bs = sm;                    // [128][BS_ROW]
    __half* As = sm + 128 * BS_ROW;     // [4][128][AS_ROW]

    const int tid = threadIdx.x;
    const int m0 = blockIdx.x * 128;
    const int yhalf = blockIdx.y;       // 0: A+bias half, 1: B half

    // ---- issue B tile: 128 k-rows x 16 chunks of 16B; 8 chunks/thread ----
    #pragma unroll
    for (int i = 0; i < 8; i++) {
        int ch = tid + i * 256;
        int k = ch >> 4, cc = ch & 15;
        cp16(Bs + k * BS_ROW + cc * 8, g_Wh + k * 256 + yhalf * 128 + cc * 8, 16);
    }
    // ---- issue A stages: each 128 rows x 4 chunks of 16B; 2 chunks/thread ----
    #pragma unroll
    for (int s = 0; s < 4; s++) {
        #pragma unroll
        for (int i = 0; i < 2; i++) {
            int ch = tid + i * 256;
            int row = ch >> 2, cc = ch & 3;
            int gr = m0 + row;
            int ok = (gr < NNODES);
            const __half* src = g_Zh + (size_t)(ok ? gr : 0) * 128 + s * 32 + cc * 8;
            cp16(As + (s * 128 + row) * AS_ROW + cc * 8, src, ok ? 16 : 0);
        }
        asm volatile("cp.async.commit_group;");
    }

    const int wid = tid >> 5;
    const int lane = tid & 31;
    const int mbase = (wid >> 1) * 32;
    const int nbase = (wid & 1) * 64;
    const int g = lane >> 2;
    const int tq = lane & 3;
    const int row_l = lane & 15;
    const int a_hi = (lane >> 4) << 3;

    float acc[2][8][4];
    #pragma unroll
    for (int mi = 0; mi < 2; mi++)
        #pragma unroll
        for (int ni = 0; ni < 8; ni++)
            #pragma unroll
            for (int c = 0; c < 4; c++) acc[mi][ni][c] = 0.f;

    #pragma unroll
    for (int s = 0; s < 4; s++) {
        if (s == 0)      asm volatile("cp.async.wait_group 3;" ::: "memory");
        else if (s == 1) asm volatile("cp.async.wait_group 2;" ::: "memory");
        else if (s == 2) asm volatile("cp.async.wait_group 1;" ::: "memory");
        else             asm volatile("cp.async.wait_group 0;" ::: "memory");
        __syncthreads();

        const __half* Ab = As + s * 128 * AS_ROW;
        #pragma unroll
        for (int ks = 0; ks < 2; ks++) {
            unsigned a[2][4];
            #pragma unroll
            for (int mi = 0; mi < 2; mi++) {
                const __half* p = Ab + (mbase + mi * 16 + row_l) * AS_ROW + ks * 16 + a_hi;
                unsigned sa = (unsigned)__cvta_generic_to_shared(p);
                asm volatile("ldmatrix.sync.aligned.m8n8.x4.shared.b16 {%0,%1,%2,%3}, [%4];"
                             : "=r"(a[mi][0]), "=r"(a[mi][1]), "=r"(a[mi][2]), "=r"(a[mi][3])
                             : "r"(sa));
            }
            unsigned bf[8][2];
            #pragma unroll
            for (int ni = 0; ni < 8; ni++) {
                const __half* p = Bs + (s * 32 + ks * 16 + row_l) * BS_ROW + nbase + ni * 8;
                unsigned sb = (unsigned)__cvta_generic_to_shared(p);
                asm volatile("ldmatrix.sync.aligned.m8n8.x2.trans.shared.b16 {%0,%1}, [%2];"
                             : "=r"(bf[ni][0]), "=r"(bf[ni][1])
                             : "r"(sb));
            }
            #pragma unroll
            for (int mi = 0; mi < 2; mi++)
                #pragma unroll
                for (int ni = 0; ni < 8; ni++)
                    mma16816(acc[mi][ni], a[mi][0], a[mi][1], a[mi][2], a[mi][3],
                             bf[ni][0], bf[ni][1]);
        }
    }

    // ---- epilogue: +bias1 (first half only), fp16 store ----
    #pragma unroll
    for (int ni = 0; ni < 8; ni++) {
        int ncol = nbase + ni * 8 + tq * 2;
        float bx = 0.f, by = 0.f;
        if (yhalf == 0) { bx = bias1[ncol]; by = bias1[ncol + 1]; }
        size_t colg = (size_t)yhalf * 128 + ncol;
        #pragma unroll
        for (int mi = 0; mi < 2; mi++) {
            int r0 = m0 + mbase + mi * 16 + g;
            if (r0 < NNODES) {
                *(__half2*)(g_ABh + (size_t)r0 * 256 + colg) =
                    __floats2half2_rn(acc[mi][ni][0] + bx, acc[mi][ni][1] + by);
            }
            int r1 = r0 + 8;
            if (r1 < NNODES) {
                *(__half2*)(g_ABh + (size_t)r1 * 256 + colg) =
                    __floats2half2_rn(acc[mi][ni][2] + bx, acc[mi][ni][3] + by);
            }
        }
    }
}

// ---------------------------------------------------------------------------
// Per-edge pass: 16 lanes per edge, 2 edges per warp, reading edge_index
// directly (no decode pass). out[e] = bias2 + sum_j W2[j]*relu(A'[src][j]+B[dst][j])
__global__ __launch_bounds__(256) void edge_kernel(
    const int* __restrict__ ei,
    const float* __restrict__ W2,
    const float* __restrict__ bias2,
    float* __restrict__ out)
{
    const int lane = threadIdx.x & 31;
    const int sl = lane & 15;
    const int sub = lane >> 4;
    const int w = (blockIdx.x * blockDim.x + threadIdx.x) >> 5;
    const int nw = (gridDim.x * blockDim.x) >> 5;

    const float4 w2a = *(const float4*)(W2 + sl * 8);
    const float4 w2b = *(const float4*)(W2 + sl * 8 + 4);
    const float b2 = bias2[0];
    const __half2 zero2 = __float2half2_rn(0.f);
    const int is64 = g_is64;
    const long long* ei64 = (const long long*)ei;

    for (int base = 2 * w; base < NEDGES; base += 2 * nw) {
        const int e = base + sub;
        int src, dst;
        if (is64) {
            src = (int)__ldg(ei64 + e);
            dst = (int)__ldg(ei64 + NEDGES + e);
        } else {
            src = __ldg(ei + e);
            dst = __ldg(ei + NEDGES + e);
        }
        uint4 av = *(const uint4*)(g_ABh + (size_t)src * 256 + sl * 8);
        uint4 bv = *(const uint4*)(g_ABh + (size_t)dst * 256 + 128 + sl * 8);
        const __half2* ah = (const __half2*)&av;
        const __half2* bh = (const __half2*)&bv;

        float2 f0 = __half22float2(__hmax2(__hadd2(ah[0], bh[0]), zero2));
        float2 f1 = __half22float2(__hmax2(__hadd2(ah[1], bh[1]), zero2));
        float2 f2 = __half22float2(__hmax2(__hadd2(ah[2], bh[2]), zero2));
        float2 f3 = __half22float2(__hmax2(__hadd2(ah[3], bh[3]), zero2));

        float acc = w2a.x * f0.x + w2a.y * f0.y + w2a.z * f1.x + w2a.w * f1.y
                  + w2b.x * f2.x + w2b.y * f2.y + w2b.z * f3.x + w2b.w * f3.y;

        acc += __shfl_xor_sync(0xffffffffu, acc, 1);
        acc += __shfl_xor_sync(0xffffffffu, acc, 2);
        acc += __shfl_xor_sync(0xffffffffu, acc, 4);
        acc += __shfl_xor_sync(0xffffffffu, acc, 8);

        if (sl == 0) out[e] = acc + b2;
    }
}

// ---------------------------------------------------------------------------
extern "C" void kernel_launch(void* const* d_in, const int* in_sizes, int n_in,
                              void* d_out, int out_size) {
    const float* z     = (const float*)d_in[0];   // [50000,128]
    const float* W1    = (const float*)d_in[1];   // [128,256]
    const float* bias1 = (const float*)d_in[2];   // [128]
    const float* W2    = (const float*)d_in[3];   // [1,128]
    const float* bias2 = (const float*)d_in[4];   // [1]
    const int*   ei    = (const int*)d_in[5];     // [2,640000]
    float* out = (float*)d_out;

    static int smem_set = 0;
    if (!smem_set) {
        cudaFuncSetAttribute(gemm_kernel,
                             cudaFuncAttributeMaxDynamicSharedMemorySize, GEMM_SMEM);
        smem_set = 1;
    }

    prep_all_kernel<<<PREP_TOTAL_BLOCKS, 256>>>(ei, z, W1);

    dim3 ggrid((NNODES + 127) / 128, 2);
    gemm_kernel<<<ggrid, 256, GEMM_SMEM>>>(bias1);

    edge_kernel<<<2368, 256>>>(ei, W2, bias2, out);
}

// round 6
// speedup vs baseline: 2.9048x; 1.0429x over previous
#include <cuda_runtime.h>
#include <cuda_fp16.h>

#define HIDDEN 128
#define NNODES 50000
#define NEDGES 640000

// Scratch (allocation-free rule: device globals)
__device__ __align__(16) __half g_ABh[NNODES * 256];  // per node: [A+bias1 (128) | B (128)], fp16
__device__ __align__(16) __half g_Wh[128 * 256];      // k-major fp16 W1: Wh[k][j]

// ---------------------------------------------------------------------------
// Prep: W1 pack only. Wh[k][j] = W1[j][k] (j<128), Wh[k][128+j] = W1[j][128+k]
__global__ __launch_bounds__(256) void pack_w1_kernel(const float* __restrict__ W1) {
    int idx = blockIdx.x * 256 + threadIdx.x;   // 128*256 total
    int k = idx >> 8;
    int j = idx & 255;
    float v = (j < 128) ? W1[j * 256 + k] : W1[(j - 128) * 256 + 128 + k];
    g_Wh[idx] = __float2half_rn(v);
}

// ---------------------------------------------------------------------------
// Tensor-core GEMM with inline Z convert: AB = fp16(Z) @ Wh.
// Block 64M x 256N, K=128 fully resident. 8 warps (2m x 4n), warp tile 32x64.
// B tile streams via cp.async from g_Wh while A is LDG(fp32)->cvt->STS(fp16).
#define AS_ROW 136   // halves per A smem row: 128 data + 8 pad (stride 17 chunks, conflict-free)
#define BS_ROW 264   // halves per B smem row: 256 data + 8 pad (stride 33 chunks, conflict-free)
#define GEMM_SMEM ((64 * AS_ROW + 128 * BS_ROW) * 2)   // 84992 bytes

__device__ __forceinline__ void cp16(__half* dst, const __half* src) {
    unsigned d = (unsigned)__cvta_generic_to_shared(dst);
    asm volatile("cp.async.cg.shared.global [%0], [%1], 16;"
                 :: "r"(d), "l"(src));
}

__device__ __forceinline__ void mma16816(float* d, unsigned a0, unsigned a1,
                                         unsigned a2, unsigned a3,
                                         unsigned b0, unsigned b1) {
    asm volatile(
        "mma.sync.aligned.m16n8k16.row.col.f32.f16.f16.f32 "
        "{%0,%1,%2,%3}, {%4,%5,%6,%7}, {%8,%9}, {%0,%1,%2,%3};"
        : "+f"(d[0]), "+f"(d[1]), "+f"(d[2]), "+f"(d[3])
        : "r"(a0), "r"(a1), "r"(a2), "r"(a3), "r"(b0), "r"(b1));
}

__global__ __launch_bounds__(256, 2) void gemm_kernel(const float* __restrict__ Z,
                                                      const float* __restrict__ bias1) {
    extern __shared__ __half sm[];
    __half* As = sm;                   // [64][AS_ROW]
    __half* Bs = sm + 64 * AS_ROW;     // [128][BS_ROW]

    const int tid = threadIdx.x;
    const int m0 = blockIdx.x * 64;

    // ---- issue B tile via cp.async: 128 k-rows x 32 chunks of 16B; 16/thread ----
    #pragma unroll
    for (int i = 0; i < 16; i++) {
        int ch = tid + i * 256;
        int k = ch >> 5, cc = ch & 31;
        cp16(Bs + k * BS_ROW + cc * 8, g_Wh + k * 256 + cc * 8);
    }
    asm volatile("cp.async.commit_group;");

    // ---- A tile: LDG fp32 -> cvt -> STS fp16. 64 rows x 32 float4; 8/thread ----
    {
        float4 v[8];
        #pragma unroll
        for (int i = 0; i < 8; i++) {
            int ch = tid + i * 256;
            int row = ch >> 5, c4 = ch & 31;
            int gr = m0 + row;
            if (gr < NNODES) v[i] = *(const float4*)(Z + (size_t)gr * HIDDEN + c4 * 4);
            else             v[i] = make_float4(0.f, 0.f, 0.f, 0.f);
        }
        #pragma unroll
        for (int i = 0; i < 8; i++) {
            int ch = tid + i * 256;
            int row = ch >> 5, c4 = ch & 31;
            __half2 h0 = __floats2half2_rn(v[i].x, v[i].y);
            __half2 h1 = __floats2half2_rn(v[i].z, v[i].w);
            __half2* d2 = (__half2*)(As + row * AS_ROW + c4 * 4);
            d2[0] = h0;
            d2[1] = h1;
        }
    }

    asm volatile("cp.async.wait_group 0;" ::: "memory");
    __syncthreads();

    const int wid = tid >> 5;
    const int lane = tid & 31;
    const int mbase = (wid >> 2) * 32;     // 0 or 32
    const int nbase = (wid & 3) * 64;      // 0,64,128,192
    const int g = lane >> 2;
    const int tq = lane & 3;
    const int row_l = lane & 15;
    const int a_hi = (lane >> 4) << 3;

    float acc[2][8][4];
    #pragma unroll
    for (int mi = 0; mi < 2; mi++)
        #pragma unroll
        for (int ni = 0; ni < 8; ni++)
            #pragma unroll
            for (int c = 0; c < 4; c++) acc[mi][ni][c] = 0.f;

    #pragma unroll
    for (int kc = 0; kc < 8; kc++) {
        unsigned a[2][4];
        #pragma unroll
        for (int mi = 0; mi < 2; mi++) {
            const __half* p = As + (mbase + mi * 16 + row_l) * AS_ROW + kc * 16 + a_hi;
            unsigned sa = (unsigned)__cvta_generic_to_shared(p);
            asm volatile("ldmatrix.sync.aligned.m8n8.x4.shared.b16 {%0,%1,%2,%3}, [%4];"
                         : "=r"(a[mi][0]), "=r"(a[mi][1]), "=r"(a[mi][2]), "=r"(a[mi][3])
                         : "r"(sa));
        }
        unsigned bf[8][2];
        #pragma unroll
        for (int ni = 0; ni < 8; ni++) {
            const __half* p = Bs + (kc * 16 + row_l) * BS_ROW + nbase + ni * 8;
            unsigned sb = (unsigned)__cvta_generic_to_shared(p);
            asm volatile("ldmatrix.sync.aligned.m8n8.x2.trans.shared.b16 {%0,%1}, [%2];"
                         : "=r"(bf[ni][0]), "=r"(bf[ni][1])
                         : "r"(sb));
        }
        #pragma unroll
        for (int mi = 0; mi < 2; mi++)
            #pragma unroll
            for (int ni = 0; ni < 8; ni++)
                mma16816(acc[mi][ni], a[mi][0], a[mi][1], a[mi][2], a[mi][3],
                         bf[ni][0], bf[ni][1]);
    }

    // ---- epilogue: +bias1 on cols <128, fp16 store to g_ABh ----
    #pragma unroll
    for (int ni = 0; ni < 8; ni++) {
        int ncol = nbase + ni * 8 + tq * 2;       // 0..255
        float bx = 0.f, by = 0.f;
        if (ncol < 128) { bx = bias1[ncol]; by = bias1[ncol + 1]; }
        #pragma unroll
        for (int mi = 0; mi < 2; mi++) {
            int r0 = m0 + mbase + mi * 16 + g;
            if (r0 < NNODES) {
                *(__half2*)(g_ABh + (size_t)r0 * 256 + ncol) =
                    __floats2half2_rn(acc[mi][ni][0] + bx, acc[mi][ni][1] + by);
            }
            int r1 = r0 + 8;
            if (r1 < NNODES) {
                *(__half2*)(g_ABh + (size_t)r1 * 256 + ncol) =
                    __floats2half2_rn(acc[mi][ni][2] + bx, acc[mi][ni][3] + by);
            }
        }
    }
}

// ---------------------------------------------------------------------------
// Per-edge pass: 16 lanes per edge, 2 edges per warp, reading edge_index
// directly. Dtype detect done per-block (ballot over first 32 odd words).
// out[e] = bias2 + sum_j W2[j]*relu(A'[src][j]+B[dst][j])   (bias1 folded in A')
__global__ __launch_bounds__(256) void edge_kernel(
    const int* __restrict__ ei,
    const float* __restrict__ W2,
    const float* __restrict__ bias2,
    float* __restrict__ out)
{
    __shared__ int s_is64;
    if (threadIdx.x < 32) {
        unsigned m = __ballot_sync(0xffffffffu, ei[2 * threadIdx.x + 1] != 0);
        if (threadIdx.x == 0) s_is64 = (m == 0) ? 1 : 0;
    }

    const int lane = threadIdx.x & 31;
    const int sl = lane & 15;
    const int sub = lane >> 4;
    const int w = (blockIdx.x * blockDim.x + threadIdx.x) >> 5;
    const int nw = (gridDim.x * blockDim.x) >> 5;

    const float4 w2a = *(const float4*)(W2 + sl * 8);
    const float4 w2b = *(const float4*)(W2 + sl * 8 + 4);
    const float b2 = bias2[0];
    const __half2 zero2 = __float2half2_rn(0.f);
    const long long* ei64 = (const long long*)ei;

    __syncthreads();
    const int is64 = s_is64;

    for (int base = 2 * w; base < NEDGES; base += 2 * nw) {
        const int e = base + sub;
        int src, dst;
        if (is64) {
            src = (int)__ldg(ei64 + e);
            dst = (int)__ldg(ei64 + NEDGES + e);
        } else {
            src = __ldg(ei + e);
            dst = __ldg(ei + NEDGES + e);
        }
        uint4 av = *(const uint4*)(g_ABh + (size_t)src * 256 + sl * 8);
        uint4 bv = *(const uint4*)(g_ABh + (size_t)dst * 256 + 128 + sl * 8);
        const __half2* ah = (const __half2*)&av;
        const __half2* bh = (const __half2*)&bv;

        float2 f0 = __half22float2(__hmax2(__hadd2(ah[0], bh[0]), zero2));
        float2 f1 = __half22float2(__hmax2(__hadd2(ah[1], bh[1]), zero2));
        float2 f2 = __half22float2(__hmax2(__hadd2(ah[2], bh[2]), zero2));
        float2 f3 = __half22float2(__hmax2(__hadd2(ah[3], bh[3]), zero2));

        float acc = w2a.x * f0.x + w2a.y * f0.y + w2a.z * f1.x + w2a.w * f1.y
                  + w2b.x * f2.x + w2b.y * f2.y + w2b.z * f3.x + w2b.w * f3.y;

        acc += __shfl_xor_sync(0xffffffffu, acc, 1);
        acc += __shfl_xor_sync(0xffffffffu, acc, 2);
        acc += __shfl_xor_sync(0xffffffffu, acc, 4);
        acc += __shfl_xor_sync(0xffffffffu, acc, 8);

        if (sl == 0) out[e] = acc + b2;
    }
}

// ---------------------------------------------------------------------------
extern "C" void kernel_launch(void* const* d_in, const int* in_sizes, int n_in,
                              void* d_out, int out_size) {
    const float* z     = (const float*)d_in[0];   // [50000,128]
    const float* W1    = (const float*)d_in[1];   // [128,256]
    const float* bias1 = (const float*)d_in[2];   // [128]
    const float* W2    = (const float*)d_in[3];   // [1,128]
    const float* bias2 = (const float*)d_in[4];   // [1]
    const int*   ei    = (const int*)d_in[5];     // [2,640000]
    float* out = (float*)d_out;

    static int smem_set = 0;
    if (!smem_set) {
        cudaFuncSetAttribute(gemm_kernel,
                             cudaFuncAttributeMaxDynamicSharedMemorySize, GEMM_SMEM);
        smem_set = 1;
    }

    pack_w1_kernel<<<128, 256>>>(W1);

    gemm_kernel<<<(NNODES + 63) / 64, 256, GEMM_SMEM>>>(z, bias1);

    edge_kernel<<<2368, 256>>>(ei, W2, bias2, out);
}